// round 2
// baseline (speedup 1.0000x reference)
#include <cuda_runtime.h>
#include <cuda_bf16.h>
#include <math.h>

// Problem constants (fixed by the reference setup_inputs()).
#define N_NODES 50000
#define N_EDGES 400000
#define NE_TOT  (N_EDGES + N_NODES)   // +self loops
#define F_IN    128
#define HID     64
#define HEADS   8
#define FEAT    (HEADS * HID)          // 512
#define N_CLASSES 16
#define NEG_SLOPE 0.2f

// ---------------------------------------------------------------------------
// Static scratch (no runtime allocation allowed).
// ---------------------------------------------------------------------------
__device__ float g_H  [(size_t)N_NODES * FEAT];     // GEMM output (per layer)
__device__ float g_O  [(size_t)N_NODES * FEAT];     // aggregation output / next GEMM input
__device__ float g_H2 [(size_t)N_NODES * N_CLASSES];
__device__ float g_als[(size_t)N_NODES * HEADS];
__device__ float g_ald[(size_t)N_NODES * HEADS];
__device__ int   g_deg   [N_NODES];
__device__ int   g_rowptr[N_NODES + 1];
__device__ int   g_cursor[N_NODES];
__device__ int   g_col   [NE_TOT];
__device__ int   g_is64;                            // 1 if edge_index is int64

__device__ __forceinline__ float eluf(float x)   { return x > 0.f ? x : expm1f(x); }
__device__ __forceinline__ float lrelu(float x)  { return x > 0.f ? x : NEG_SLOPE * x; }

__device__ __forceinline__ int clampi(int v) {
    return (v < 0) ? 0 : (v >= N_NODES ? N_NODES - 1 : v);
}

// Fetch edge endpoint 'idx' from the raw buffer honoring detected dtype.
__device__ __forceinline__ int edge_at(const void* ei, int idx, int is64) {
    if (is64) return clampi((int)((const long long*)ei)[idx]);
    return clampi(((const int*)ei)[idx]);
}

// ---------------------------------------------------------------------------
// Dtype probe: int64 layout => odd 32-bit words (high halves) are all zero.
// ---------------------------------------------------------------------------
__global__ void detect_dtype_kernel(const int* __restrict__ ei_raw) {
    if (threadIdx.x != 0 || blockIdx.x != 0) return;
    int any_nonzero = 0;
    #pragma unroll 1
    for (int k = 0; k < 64; k++)
        any_nonzero |= ei_raw[2 * k + 1];
    g_is64 = (any_nonzero == 0) ? 1 : 0;
}

// ---------------------------------------------------------------------------
// CSR build (by destination node)
// ---------------------------------------------------------------------------
__global__ void zero_deg_kernel() {
    int i = blockIdx.x * blockDim.x + threadIdx.x;
    if (i < N_NODES) g_deg[i] = 0;
}

__global__ void count_kernel(const void* __restrict__ ei) {
    int e = blockIdx.x * blockDim.x + threadIdx.x;
    if (e >= NE_TOT) return;
    int is64 = g_is64;
    int dst = (e < N_EDGES) ? edge_at(ei, N_EDGES + e, is64) : (e - N_EDGES);
    atomicAdd(&g_deg[dst], 1);
}

// Single-block exclusive scan of g_deg -> g_rowptr (and g_cursor copy).
__global__ void scan_kernel() {
    __shared__ int sm[1024];
    __shared__ int carry;
    int tid = threadIdx.x;
    if (tid == 0) carry = 0;
    __syncthreads();
    for (int base = 0; base < N_NODES; base += 1024) {
        int cbase = carry;
        int i = base + tid;
        int v = (i < N_NODES) ? g_deg[i] : 0;
        sm[tid] = v;
        __syncthreads();
        #pragma unroll
        for (int off = 1; off < 1024; off <<= 1) {
            int t = (tid >= off) ? sm[tid - off] : 0;
            __syncthreads();
            sm[tid] += t;
            __syncthreads();
        }
        int incl = sm[tid];
        if (i < N_NODES) {
            int excl = incl - v + cbase;
            g_rowptr[i] = excl;
            g_cursor[i] = excl;
        }
        __syncthreads();
        if (tid == 0) carry = cbase + sm[1023];
        __syncthreads();
    }
    if (tid == 0) g_rowptr[N_NODES] = carry;
}

__global__ void fill_kernel(const void* __restrict__ ei) {
    int e = blockIdx.x * blockDim.x + threadIdx.x;
    if (e >= NE_TOT) return;
    int is64 = g_is64;
    int src, dst;
    if (e < N_EDGES) {
        src = edge_at(ei, e, is64);
        dst = edge_at(ei, N_EDGES + e, is64);
    } else {
        src = dst = e - N_EDGES;
    }
    int pos = atomicAdd(&g_cursor[dst], 1);
    if (pos >= 0 && pos < NE_TOT) g_col[pos] = src;
}

// ---------------------------------------------------------------------------
// fp32 SGEMM: C[M,N] = act(A)[M,K] @ B[K,N].  BM=BN=128, BK=8, 8x8 microtile.
// N must be a multiple of 128, K a multiple of 8.  ELU applied on A-load.
// ---------------------------------------------------------------------------
template<bool ELU>
__global__ __launch_bounds__(256) void sgemm_kernel(
    const float* __restrict__ A, const float* __restrict__ B,
    float* __restrict__ C, int M, int N, int K)
{
    __shared__ float As[8][128];
    __shared__ float Bs[8][128];
    int tid = threadIdx.x;
    int tx = tid & 15, ty = tid >> 4;
    int brow = blockIdx.y, bcol = blockIdx.x;

    float acc[8][8] = {};

    int arow = tid >> 1;                 // 0..127
    int acol = (tid & 1) << 2;           // 0 or 4
    int grow = brow * 128 + arow;
    int bro = tid >> 5;                  // 0..7
    int bco = (tid & 31) << 2;           // 0..124

    for (int k0 = 0; k0 < K; k0 += 8) {
        float4 av = make_float4(0.f, 0.f, 0.f, 0.f);
        if (grow < M)
            av = *(const float4*)(A + (size_t)grow * K + k0 + acol);
        if (ELU) {
            av.x = eluf(av.x); av.y = eluf(av.y);
            av.z = eluf(av.z); av.w = eluf(av.w);
        }
        As[acol + 0][arow] = av.x;
        As[acol + 1][arow] = av.y;
        As[acol + 2][arow] = av.z;
        As[acol + 3][arow] = av.w;
        float4 bv = *(const float4*)(B + (size_t)(k0 + bro) * N + bcol * 128 + bco);
        *(float4*)&Bs[bro][bco] = bv;
        __syncthreads();

        #pragma unroll
        for (int kk = 0; kk < 8; kk++) {
            float ra[8], rb[8];
            *(float4*)&ra[0] = *(const float4*)&As[kk][ty * 8];
            *(float4*)&ra[4] = *(const float4*)&As[kk][ty * 8 + 4];
            *(float4*)&rb[0] = *(const float4*)&Bs[kk][tx * 8];
            *(float4*)&rb[4] = *(const float4*)&Bs[kk][tx * 8 + 4];
            #pragma unroll
            for (int i = 0; i < 8; i++)
                #pragma unroll
                for (int j = 0; j < 8; j++)
                    acc[i][j] = fmaf(ra[i], rb[j], acc[i][j]);
        }
        __syncthreads();
    }

    #pragma unroll
    for (int i = 0; i < 8; i++) {
        int r = brow * 128 + ty * 8 + i;
        if (r >= M) continue;
        int cbase = bcol * 128 + tx * 8;
        #pragma unroll
        for (int j = 0; j < 8; j += 4)
            *(float4*)(C + (size_t)r * N + cbase + j) = *(float4*)&acc[i][j];
    }
}

// Small GEMM for layer 2: [M,512] @ [512,16], ELU on A.
__global__ __launch_bounds__(128) void gemm_small_kernel(
    const float* __restrict__ A, const float* __restrict__ W,
    float* __restrict__ C, int M)
{
    __shared__ float xs[8 * 512];
    int r0 = blockIdx.x * 8;
    int tid = threadIdx.x;
    for (int i = tid; i < 8 * 512; i += 128) {
        int rr = i >> 9, cc = i & 511;
        float v = (r0 + rr < M) ? A[(size_t)(r0 + rr) * 512 + cc] : 0.f;
        xs[i] = eluf(v);
    }
    __syncthreads();
    int r = tid >> 4, c = tid & 15;
    float acc = 0.f;
    const float* xr = &xs[r * 512];
    #pragma unroll 8
    for (int k = 0; k < 512; k++)
        acc = fmaf(xr[k], W[k * 16 + c], acc);
    if (r0 + r < M) C[(size_t)(r0 + r) * 16 + c] = acc;
}

// ---------------------------------------------------------------------------
// Attention logit projections: als[n,h] = h[n,h,:]·a_s[h,:], same for ald.
// One warp per (node, head).
// ---------------------------------------------------------------------------
template<int H, int C>
__global__ void al_kernel(const float* __restrict__ h,
                          const float* __restrict__ a_s,
                          const float* __restrict__ a_d,
                          float* __restrict__ als, float* __restrict__ ald)
{
    int wid = (blockIdx.x * blockDim.x + threadIdx.x) >> 5;
    int lane = threadIdx.x & 31;
    if (wid >= N_NODES * H) return;
    int n = wid / H, hd = wid % H;
    const float* hr = h + (size_t)n * H * C + hd * C;
    float s = 0.f, d = 0.f;
    for (int c = lane; c < C; c += 32) {
        float v = hr[c];
        s = fmaf(v, a_s[hd * C + c], s);
        d = fmaf(v, a_d[hd * C + c], d);
    }
    #pragma unroll
    for (int o = 16; o; o >>= 1) {
        s += __shfl_xor_sync(0xFFFFFFFFu, s, o);
        d += __shfl_xor_sync(0xFFFFFFFFu, d, o);
    }
    if (lane == 0) { als[wid] = s; ald[wid] = d; }
}

// ---------------------------------------------------------------------------
// Per-destination softmax + aggregation (H=8, C=64).  One block per node,
// 128 threads, each owning channels {tid, tid+128, tid+256, tid+384}.
// out[n,c] = (sum_e exp(e_e - max) * h[src_e, c]) / denom + bias[c]
// ---------------------------------------------------------------------------
__global__ __launch_bounds__(128) void agg_kernel(
    const float* __restrict__ h, const float* __restrict__ als,
    const float* __restrict__ ald, const float* __restrict__ bias,
    float* __restrict__ out)
{
    int n = blockIdx.x;
    int tid = threadIdx.x;
    int start = g_rowptr[n], end = g_rowptr[n + 1];

    int hh[4];
    float ad[4], mx[4];
    #pragma unroll
    for (int k = 0; k < 4; k++) {
        int c = tid + 128 * k;
        hh[k] = c >> 6;
        ad[k] = ald[n * 8 + hh[k]];
        mx[k] = -1e30f;
    }
    for (int i = start; i < end; i++) {
        int s = g_col[i];
        #pragma unroll
        for (int k = 0; k < 4; k++) {
            float e = lrelu(als[s * 8 + hh[k]] + ad[k]);
            mx[k] = fmaxf(mx[k], e);
        }
    }
    float acc[4] = {0.f, 0.f, 0.f, 0.f};
    float den[4] = {0.f, 0.f, 0.f, 0.f};
    for (int i = start; i < end; i++) {
        int s = g_col[i];
        const float* hr = h + (size_t)s * FEAT;
        #pragma unroll
        for (int k = 0; k < 4; k++) {
            float e = lrelu(als[s * 8 + hh[k]] + ad[k]);
            float ex = __expf(e - mx[k]);
            den[k] += ex;
            acc[k] = fmaf(ex, hr[tid + 128 * k], acc[k]);
        }
    }
    #pragma unroll
    for (int k = 0; k < 4; k++) {
        int c = tid + 128 * k;
        out[(size_t)n * FEAT + c] = acc[k] / den[k] + bias[c];
    }
}

// Final layer aggregation (H=1, C=16).  One warp per node.
__global__ __launch_bounds__(128) void agg_final_kernel(
    const float* __restrict__ h2, const float* __restrict__ als,
    const float* __restrict__ ald, const float* __restrict__ bias,
    float* __restrict__ out)
{
    int wid = (blockIdx.x * blockDim.x + threadIdx.x) >> 5;
    int lane = threadIdx.x & 31;
    if (wid >= N_NODES) return;
    int n = wid;
    int start = g_rowptr[n], end = g_rowptr[n + 1];
    float adv = ald[n];
    float mx = -1e30f;
    for (int i = start; i < end; i++) {
        float e = lrelu(als[g_col[i]] + adv);
        mx = fmaxf(mx, e);
    }
    float acc = 0.f, den = 0.f;
    for (int i = start; i < end; i++) {
        int s = g_col[i];
        float e = lrelu(als[s] + adv);
        float ex = __expf(e - mx);
        den += ex;
        if (lane < 16) acc = fmaf(ex, h2[(size_t)s * 16 + lane], acc);
    }
    if (lane < 16) out[(size_t)n * 16 + lane] = acc / den + bias[lane];
}

// ---------------------------------------------------------------------------
// Launch
// ---------------------------------------------------------------------------
extern "C" void kernel_launch(void* const* d_in, const int* in_sizes, int n_in,
                              void* d_out, int out_size)
{
    const float* x    = (const float*)d_in[0];
    const void*  ei   = d_in[1];              // int32 or int64, autodetected
    const float* W0   = (const float*)d_in[2];
    const float* a_s0 = (const float*)d_in[3];
    const float* a_d0 = (const float*)d_in[4];
    const float* b0   = (const float*)d_in[5];
    const float* W1   = (const float*)d_in[6];
    const float* a_s1 = (const float*)d_in[7];
    const float* a_d1 = (const float*)d_in[8];
    const float* b1   = (const float*)d_in[9];
    const float* W2   = (const float*)d_in[10];
    const float* a_s2 = (const float*)d_in[11];
    const float* a_d2 = (const float*)d_in[12];
    const float* b2   = (const float*)d_in[13];
    float*       out  = (float*)d_out;

    float *H, *O, *H2, *ALS, *ALD;
    cudaGetSymbolAddress((void**)&H,   g_H);
    cudaGetSymbolAddress((void**)&O,   g_O);
    cudaGetSymbolAddress((void**)&H2,  g_H2);
    cudaGetSymbolAddress((void**)&ALS, g_als);
    cudaGetSymbolAddress((void**)&ALD, g_ald);

    // --- CSR by destination ---
    detect_dtype_kernel<<<1, 1>>>((const int*)ei);
    zero_deg_kernel<<<(N_NODES + 255) / 256, 256>>>();
    count_kernel<<<(NE_TOT + 255) / 256, 256>>>(ei);
    scan_kernel<<<1, 1024>>>();
    fill_kernel<<<(NE_TOT + 255) / 256, 256>>>(ei);

    dim3 g512(FEAT / 128, (N_NODES + 127) / 128);

    // --- Layer 0 ---
    sgemm_kernel<false><<<g512, 256>>>(x, W0, H, N_NODES, FEAT, F_IN);
    al_kernel<HEADS, HID><<<(N_NODES * HEADS * 32 + 255) / 256, 256>>>(H, a_s0, a_d0, ALS, ALD);
    agg_kernel<<<N_NODES, 128>>>(H, ALS, ALD, b0, O);

    // --- Layer 1 (ELU fused into GEMM A-load) ---
    sgemm_kernel<true><<<g512, 256>>>(O, W1, H, N_NODES, FEAT, FEAT);
    al_kernel<HEADS, HID><<<(N_NODES * HEADS * 32 + 255) / 256, 256>>>(H, a_s1, a_d1, ALS, ALD);
    agg_kernel<<<N_NODES, 128>>>(H, ALS, ALD, b1, O);

    // --- Layer 2 ---
    gemm_small_kernel<<<(N_NODES + 7) / 8, 128>>>(O, W2, H2, N_NODES);
    al_kernel<1, N_CLASSES><<<(N_NODES * 32 + 255) / 256, 256>>>(H2, a_s2, a_d2, ALS, ALD);
    agg_final_kernel<<<(N_NODES * 32 + 127) / 128, 128>>>(H2, ALS, ALD, b2, out);
}

// round 3
// speedup vs baseline: 1.2158x; 1.2158x over previous
#include <cuda_runtime.h>
#include <cuda_bf16.h>
#include <mma.h>
#include <math.h>

using namespace nvcuda;

// Problem constants (fixed by the reference setup_inputs()).
#define N_NODES 50000
#define M_PAD   50048                 // padded to multiple of 128 for tensor GEMM
#define N_EDGES 400000
#define NE_TOT  (N_EDGES + N_NODES)   // +self loops
#define F_IN    128
#define HID     64
#define HEADS   8
#define FEAT    (HEADS * HID)          // 512
#define N_CLASSES 16
#define NEG_SLOPE 0.2f

// ---------------------------------------------------------------------------
// Static scratch (no runtime allocation allowed).
// ---------------------------------------------------------------------------
__device__ float g_H  [(size_t)M_PAD * FEAT];       // GEMM output (per layer)
__device__ float g_O  [(size_t)M_PAD * FEAT];       // aggregation output / next GEMM input
__device__ float g_H2 [(size_t)N_NODES * N_CLASSES];
__device__ float g_als[(size_t)N_NODES * HEADS];
__device__ float g_ald[(size_t)N_NODES * HEADS];
__device__ int   g_deg   [N_NODES];
__device__ int   g_rowptr[N_NODES + 1];
__device__ int   g_cursor[N_NODES];
__device__ int   g_col   [NE_TOT];
__device__ int   g_is64;                            // 1 if edge_index is int64

__device__ __forceinline__ float eluf(float x)   { return x > 0.f ? x : expm1f(x); }
__device__ __forceinline__ float lrelu(float x)  { return x > 0.f ? x : NEG_SLOPE * x; }

__device__ __forceinline__ int clampi(int v) {
    return (v < 0) ? 0 : (v >= N_NODES ? N_NODES - 1 : v);
}

__device__ __forceinline__ int edge_at(const void* ei, int idx, int is64) {
    if (is64) return clampi((int)((const long long*)ei)[idx]);
    return clampi(((const int*)ei)[idx]);
}

// ---------------------------------------------------------------------------
// Dtype probe: int64 layout => odd 32-bit words (high halves) are all zero.
// ---------------------------------------------------------------------------
__global__ void detect_dtype_kernel(const int* __restrict__ ei_raw) {
    if (threadIdx.x != 0 || blockIdx.x != 0) return;
    int any_nonzero = 0;
    #pragma unroll 1
    for (int k = 0; k < 64; k++)
        any_nonzero |= ei_raw[2 * k + 1];
    g_is64 = (any_nonzero == 0) ? 1 : 0;
}

// ---------------------------------------------------------------------------
// CSR build (by destination node)
// ---------------------------------------------------------------------------
__global__ void zero_deg_kernel() {
    int i = blockIdx.x * blockDim.x + threadIdx.x;
    if (i < N_NODES) g_deg[i] = 0;
}

__global__ void count_kernel(const void* __restrict__ ei) {
    int e = blockIdx.x * blockDim.x + threadIdx.x;
    if (e >= NE_TOT) return;
    int is64 = g_is64;
    int dst = (e < N_EDGES) ? edge_at(ei, N_EDGES + e, is64) : (e - N_EDGES);
    atomicAdd(&g_deg[dst], 1);
}

// Exclusive scan of g_deg -> g_rowptr/g_cursor.  Chunked sequential + warp scan.
__global__ void scan_kernel() {
    const int T = 1024;
    const int CH = (N_NODES + T - 1) / T;   // 49
    __shared__ int wsum[32];
    int t = threadIdx.x;
    int b = t * CH;
    int e = min(b + CH, N_NODES);
    int s = 0;
    for (int i = b; i < e; i++) s += g_deg[i];
    int lane = t & 31, w = t >> 5;
    int v = s;
    #pragma unroll
    for (int o = 1; o < 32; o <<= 1) {
        int u = __shfl_up_sync(0xFFFFFFFFu, v, o);
        if (lane >= o) v += u;
    }
    if (lane == 31) wsum[w] = v;
    __syncthreads();
    if (w == 0) {
        int x = wsum[lane];
        #pragma unroll
        for (int o = 1; o < 32; o <<= 1) {
            int u = __shfl_up_sync(0xFFFFFFFFu, x, o);
            if (lane >= o) x += u;
        }
        wsum[lane] = x;
    }
    __syncthreads();
    int excl = v - s + (w > 0 ? wsum[w - 1] : 0);
    int run = excl;
    for (int i = b; i < e; i++) {
        int d = g_deg[i];
        g_rowptr[i] = run;
        g_cursor[i] = run;
        run += d;
    }
    if (t == T - 1) g_rowptr[N_NODES] = run;
}

__global__ void fill_kernel(const void* __restrict__ ei) {
    int e = blockIdx.x * blockDim.x + threadIdx.x;
    if (e >= NE_TOT) return;
    int is64 = g_is64;
    int src, dst;
    if (e < N_EDGES) {
        src = edge_at(ei, e, is64);
        dst = edge_at(ei, N_EDGES + e, is64);
    } else {
        src = dst = e - N_EDGES;
    }
    int pos = atomicAdd(&g_cursor[dst], 1);
    if (pos >= 0 && pos < NE_TOT) g_col[pos] = src;
}

// ---------------------------------------------------------------------------
// Tensor-core tf32 GEMM: C[M_PAD, N] = act(A)[M, K] @ B[K, N]
// BM=128, BN=64, BK=32; 8 warps, each computing 32x32 (2x2 wmma 16x16x8).
// A rows >= M are zero-filled; C is a padded scratch buffer (no store guard).
// ---------------------------------------------------------------------------
#define BM 128
#define BN 64
#define BK 32
#define LDA (BK + 8)     // 40
#define LDB (BN + 8)     // 72

template<bool ELU>
__global__ __launch_bounds__(256) void tf32_gemm_kernel(
    const float* __restrict__ A, const float* __restrict__ B,
    float* __restrict__ C, int M, int N, int K)
{
    __shared__ float As[BM][LDA];
    __shared__ float Bs[BK][LDB];
    int tid  = threadIdx.x;
    int warp = tid >> 5;
    int wm   = warp >> 1;     // 0..3 -> M offset wm*32
    int wn   = warp & 1;      // 0..1 -> N offset wn*32
    int row0 = blockIdx.y * BM;
    int col0 = blockIdx.x * BN;

    wmma::fragment<wmma::accumulator, 16, 16, 8, float> acc[2][2];
    #pragma unroll
    for (int i = 0; i < 2; i++)
        #pragma unroll
        for (int j = 0; j < 2; j++)
            wmma::fill_fragment(acc[i][j], 0.0f);

    for (int k0 = 0; k0 < K; k0 += BK) {
        // Load A tile: 128 x 32 floats (1024 float4), 256 threads x 4.
        #pragma unroll
        for (int it = tid; it < BM * BK / 4; it += 256) {
            int r  = it >> 3;          // 8 float4 per row
            int cq = (it & 7) << 2;
            float4 v = make_float4(0.f, 0.f, 0.f, 0.f);
            if (row0 + r < M)
                v = *(const float4*)(A + (size_t)(row0 + r) * K + k0 + cq);
            if (ELU) {
                v.x = eluf(v.x); v.y = eluf(v.y);
                v.z = eluf(v.z); v.w = eluf(v.w);
            }
            *(float4*)&As[r][cq] = v;
        }
        // Load B tile: 32 x 64 floats (512 float4), 256 threads x 2.
        #pragma unroll
        for (int it = tid; it < BK * BN / 4; it += 256) {
            int r  = it >> 4;          // 16 float4 per row
            int cq = (it & 15) << 2;
            float4 v = *(const float4*)(B + (size_t)(k0 + r) * N + col0 + cq);
            *(float4*)&Bs[r][cq] = v;
        }
        __syncthreads();

        #pragma unroll
        for (int kk = 0; kk < BK; kk += 8) {
            wmma::fragment<wmma::matrix_a, 16, 16, 8, wmma::precision::tf32, wmma::row_major> af[2];
            wmma::fragment<wmma::matrix_b, 16, 16, 8, wmma::precision::tf32, wmma::row_major> bf[2];
            #pragma unroll
            for (int i = 0; i < 2; i++) {
                wmma::load_matrix_sync(af[i], &As[wm * 32 + i * 16][kk], LDA);
                #pragma unroll
                for (int u = 0; u < af[i].num_elements; u++)
                    af[i].x[u] = wmma::__float_to_tf32(af[i].x[u]);
            }
            #pragma unroll
            for (int j = 0; j < 2; j++) {
                wmma::load_matrix_sync(bf[j], &Bs[kk][wn * 32 + j * 16], LDB);
                #pragma unroll
                for (int u = 0; u < bf[j].num_elements; u++)
                    bf[j].x[u] = wmma::__float_to_tf32(bf[j].x[u]);
            }
            #pragma unroll
            for (int i = 0; i < 2; i++)
                #pragma unroll
                for (int j = 0; j < 2; j++)
                    wmma::mma_sync(acc[i][j], af[i], bf[j], acc[i][j]);
        }
        __syncthreads();
    }

    #pragma unroll
    for (int i = 0; i < 2; i++)
        #pragma unroll
        for (int j = 0; j < 2; j++)
            wmma::store_matrix_sync(
                C + (size_t)(row0 + wm * 32 + i * 16) * N + col0 + wn * 32 + j * 16,
                acc[i][j], N, wmma::mem_row_major);
}

// Small GEMM for layer 2: [M,512] @ [512,16], ELU on A.
__global__ __launch_bounds__(128) void gemm_small_kernel(
    const float* __restrict__ A, const float* __restrict__ W,
    float* __restrict__ C, int M)
{
    __shared__ float xs[8 * 512];
    int r0 = blockIdx.x * 8;
    int tid = threadIdx.x;
    for (int i = tid; i < 8 * 512; i += 128) {
        int rr = i >> 9, cc = i & 511;
        float v = (r0 + rr < M) ? A[(size_t)(r0 + rr) * 512 + cc] : 0.f;
        xs[i] = eluf(v);
    }
    __syncthreads();
    int r = tid >> 4, c = tid & 15;
    float acc = 0.f;
    const float* xr = &xs[r * 512];
    #pragma unroll 8
    for (int k = 0; k < 512; k++)
        acc = fmaf(xr[k], W[k * 16 + c], acc);
    if (r0 + r < M) C[(size_t)(r0 + r) * 16 + c] = acc;
}

// ---------------------------------------------------------------------------
// Attention logit projections: als[n,h] = h[n,h,:]·a_s[h,:], same for ald.
// One warp per (node, head).
// ---------------------------------------------------------------------------
template<int H, int C>
__global__ void al_kernel(const float* __restrict__ h,
                          const float* __restrict__ a_s,
                          const float* __restrict__ a_d,
                          float* __restrict__ als, float* __restrict__ ald)
{
    int wid = (blockIdx.x * blockDim.x + threadIdx.x) >> 5;
    int lane = threadIdx.x & 31;
    if (wid >= N_NODES * H) return;
    int n = wid / H, hd = wid % H;
    const float* hr = h + (size_t)n * H * C + hd * C;
    float s = 0.f, d = 0.f;
    for (int c = lane; c < C; c += 32) {
        float v = hr[c];
        s = fmaf(v, a_s[hd * C + c], s);
        d = fmaf(v, a_d[hd * C + c], d);
    }
    #pragma unroll
    for (int o = 16; o; o >>= 1) {
        s += __shfl_xor_sync(0xFFFFFFFFu, s, o);
        d += __shfl_xor_sync(0xFFFFFFFFu, d, o);
    }
    if (lane == 0) { als[wid] = s; ald[wid] = d; }
}

// ---------------------------------------------------------------------------
// Per-destination softmax + aggregation (H=8, C=64).  One block per node,
// 128 threads; thread t owns head t>>4, 4 contiguous channels (t&15)*4.
// Softmax shifted by the self-loop logit (shift-invariant, no max pass).
// ---------------------------------------------------------------------------
__global__ __launch_bounds__(128) void agg_kernel(
    const float* __restrict__ h, const float* __restrict__ als,
    const float* __restrict__ ald, const float* __restrict__ bias,
    float* __restrict__ out)
{
    int n = blockIdx.x;
    int t = threadIdx.x;
    int hd = t >> 4;
    int c4 = (t & 15) << 2;
    int start = g_rowptr[n], end = g_rowptr[n + 1];

    float adv = ald[n * 8 + hd];
    float shift = lrelu(als[n * 8 + hd] + adv);   // self-loop logit

    float4 acc = make_float4(0.f, 0.f, 0.f, 0.f);
    float den = 0.f;
    for (int i = start; i < end; i++) {
        int s = g_col[i];
        float w = __expf(lrelu(als[s * 8 + hd] + adv) - shift);
        den += w;
        const float4 hv = *(const float4*)(h + (size_t)s * FEAT + hd * 64 + c4);
        acc.x = fmaf(w, hv.x, acc.x);
        acc.y = fmaf(w, hv.y, acc.y);
        acc.z = fmaf(w, hv.z, acc.z);
        acc.w = fmaf(w, hv.w, acc.w);
    }
    float inv = 1.f / den;
    int c = hd * 64 + c4;
    float* op = out + (size_t)n * FEAT + c;
    op[0] = acc.x * inv + bias[c + 0];
    op[1] = acc.y * inv + bias[c + 1];
    op[2] = acc.z * inv + bias[c + 2];
    op[3] = acc.w * inv + bias[c + 3];
}

// Final layer aggregation (H=1, C=16).  One warp per node, self-shifted softmax.
__global__ __launch_bounds__(128) void agg_final_kernel(
    const float* __restrict__ h2, const float* __restrict__ als,
    const float* __restrict__ ald, const float* __restrict__ bias,
    float* __restrict__ out)
{
    int wid = (blockIdx.x * blockDim.x + threadIdx.x) >> 5;
    int lane = threadIdx.x & 31;
    if (wid >= N_NODES) return;
    int n = wid;
    int start = g_rowptr[n], end = g_rowptr[n + 1];
    float adv = ald[n];
    float shift = lrelu(als[n] + adv);
    float acc = 0.f, den = 0.f;
    for (int i = start; i < end; i++) {
        int s = g_col[i];
        float w = __expf(lrelu(als[s] + adv) - shift);
        den += w;
        if (lane < 16) acc = fmaf(w, h2[(size_t)s * 16 + lane], acc);
    }
    if (lane < 16) out[(size_t)n * 16 + lane] = acc / den + bias[lane];
}

// ---------------------------------------------------------------------------
// Launch
// ---------------------------------------------------------------------------
extern "C" void kernel_launch(void* const* d_in, const int* in_sizes, int n_in,
                              void* d_out, int out_size)
{
    const float* x    = (const float*)d_in[0];
    const void*  ei   = d_in[1];              // int32 or int64, autodetected
    const float* W0   = (const float*)d_in[2];
    const float* a_s0 = (const float*)d_in[3];
    const float* a_d0 = (const float*)d_in[4];
    const float* b0   = (const float*)d_in[5];
    const float* W1   = (const float*)d_in[6];
    const float* a_s1 = (const float*)d_in[7];
    const float* a_d1 = (const float*)d_in[8];
    const float* b1   = (const float*)d_in[9];
    const float* W2   = (const float*)d_in[10];
    const float* a_s2 = (const float*)d_in[11];
    const float* a_d2 = (const float*)d_in[12];
    const float* b2   = (const float*)d_in[13];
    float*       out  = (float*)d_out;

    float *H, *O, *H2, *ALS, *ALD;
    cudaGetSymbolAddress((void**)&H,   g_H);
    cudaGetSymbolAddress((void**)&O,   g_O);
    cudaGetSymbolAddress((void**)&H2,  g_H2);
    cudaGetSymbolAddress((void**)&ALS, g_als);
    cudaGetSymbolAddress((void**)&ALD, g_ald);

    // --- CSR by destination ---
    detect_dtype_kernel<<<1, 1>>>((const int*)ei);
    zero_deg_kernel<<<(N_NODES + 255) / 256, 256>>>();
    count_kernel<<<(NE_TOT + 255) / 256, 256>>>(ei);
    scan_kernel<<<1, 1024>>>();
    fill_kernel<<<(NE_TOT + 255) / 256, 256>>>(ei);

    dim3 ggemm(FEAT / BN, M_PAD / BM);   // (8, 391)

    // --- Layer 0 ---
    tf32_gemm_kernel<false><<<ggemm, 256>>>(x, W0, H, N_NODES, FEAT, F_IN);
    al_kernel<HEADS, HID><<<(N_NODES * HEADS * 32 + 255) / 256, 256>>>(H, a_s0, a_d0, ALS, ALD);
    agg_kernel<<<N_NODES, 128>>>(H, ALS, ALD, b0, O);

    // --- Layer 1 (ELU fused into GEMM A-load) ---
    tf32_gemm_kernel<true><<<ggemm, 256>>>(O, W1, H, N_NODES, FEAT, FEAT);
    al_kernel<HEADS, HID><<<(N_NODES * HEADS * 32 + 255) / 256, 256>>>(H, a_s1, a_d1, ALS, ALD);
    agg_kernel<<<N_NODES, 128>>>(H, ALS, ALD, b1, O);

    // --- Layer 2 ---
    gemm_small_kernel<<<(N_NODES + 7) / 8, 128>>>(O, W2, H2, N_NODES);
    al_kernel<1, N_CLASSES><<<(N_NODES * 32 + 255) / 256, 256>>>(H2, a_s2, a_d2, ALS, ALD);
    agg_final_kernel<<<(N_NODES * 32 + 127) / 128, 128>>>(H2, ALS, ALD, b2, out);
}

// round 4
// speedup vs baseline: 2.1198x; 1.7435x over previous
#include <cuda_runtime.h>
#include <cuda_bf16.h>
#include <mma.h>
#include <math.h>
#include <stdint.h>

using namespace nvcuda;

#define N_NODES 50000
#define M_PAD   50048
#define N_EDGES 400000
#define NE_TOT  (N_EDGES + N_NODES)
#define F_IN    128
#define HID     64
#define HEADS   8
#define FEAT    (HEADS * HID)          // 512
#define N_CLASSES 16
#define NEG_SLOPE 0.2f

// ---------------------------------------------------------------------------
// Static scratch
// ---------------------------------------------------------------------------
__device__ float g_H  [(size_t)M_PAD * FEAT];
__device__ float g_O  [(size_t)M_PAD * FEAT];       // ELU'd aggregation output
__device__ float g_H2 [(size_t)M_PAD * N_CLASSES];
__device__ float g_als[(size_t)N_NODES * HEADS];
__device__ float g_ald[(size_t)N_NODES * HEADS];
__device__ int   g_deg   [N_NODES];
__device__ int   g_rowptr[N_NODES + 1];
__device__ int   g_cursor[N_NODES];
__device__ int   g_col   [NE_TOT];
__device__ int   g_bsum  [256];
__device__ int   g_is64;

__device__ __forceinline__ float eluf(float x)   { return x > 0.f ? x : expm1f(x); }
__device__ __forceinline__ float lrelu(float x)  { return x > 0.f ? x : NEG_SLOPE * x; }
__device__ __forceinline__ int clampi(int v) {
    return (v < 0) ? 0 : (v >= N_NODES ? N_NODES - 1 : v);
}
__device__ __forceinline__ int edge_at(const void* ei, int idx, int is64) {
    if (is64) return clampi((int)((const long long*)ei)[idx]);
    return clampi(((const int*)ei)[idx]);
}

__device__ __forceinline__ void cp_async16(uint32_t saddr, const void* gptr, int src_bytes) {
    asm volatile("cp.async.cg.shared.global [%0], [%1], 16, %2;\n"
                 :: "r"(saddr), "l"(gptr), "r"(src_bytes));
}
__device__ __forceinline__ void cp_commit() {
    asm volatile("cp.async.commit_group;\n");
}

// ---------------------------------------------------------------------------
// zero degrees + dtype probe (int64 layout => odd 32-bit words all zero)
// ---------------------------------------------------------------------------
__global__ void zero_detect_kernel(const int* __restrict__ ei_raw) {
    int i = blockIdx.x * blockDim.x + threadIdx.x;
    if (i < N_NODES) g_deg[i] = 0;
    if (i == 0) {
        int any_nonzero = 0;
        #pragma unroll 1
        for (int k = 0; k < 64; k++) any_nonzero |= ei_raw[2 * k + 1];
        g_is64 = (any_nonzero == 0) ? 1 : 0;
    }
}

__global__ void count_kernel(const void* __restrict__ ei) {
    int e = blockIdx.x * blockDim.x + threadIdx.x;
    if (e >= NE_TOT) return;
    int is64 = g_is64;
    int dst = (e < N_EDGES) ? edge_at(ei, N_EDGES + e, is64) : (e - N_EDGES);
    atomicAdd(&g_deg[dst], 1);
}

// ---------------------------------------------------------------------------
// Parallel exclusive scan: per-block sums -> 1-block scan -> per-block write
// ---------------------------------------------------------------------------
#define SCH 256
#define SNB ((N_NODES + SCH - 1) / SCH)   // 196

__device__ __forceinline__ int block_excl_scan256(int v, int t) {
    __shared__ int ws[8];
    int lane = t & 31, w = t >> 5;
    int x = v;
    #pragma unroll
    for (int o = 1; o < 32; o <<= 1) {
        int u = __shfl_up_sync(0xFFFFFFFFu, x, o);
        if (lane >= o) x += u;
    }
    if (lane == 31) ws[w] = x;
    __syncthreads();
    if (w == 0) {
        int y = (lane < 8) ? ws[lane] : 0;
        #pragma unroll
        for (int o = 1; o < 8; o <<= 1) {
            int u = __shfl_up_sync(0xFFFFFFFFu, y, o);
            if (lane >= o) y += u;
        }
        if (lane < 8) ws[lane] = y;
    }
    __syncthreads();
    int base = (w > 0) ? ws[w - 1] : 0;
    return base + x - v;
}

__global__ void psum_kernel() {
    int b = blockIdx.x, t = threadIdx.x;
    int i = b * SCH + t;
    int v = (i < N_NODES) ? g_deg[i] : 0;
    __shared__ int ws[8];
    int lane = t & 31, w = t >> 5;
    #pragma unroll
    for (int o = 16; o; o >>= 1) v += __shfl_xor_sync(0xFFFFFFFFu, v, o);
    if (lane == 0) ws[w] = v;
    __syncthreads();
    if (t == 0) {
        int s = 0;
        #pragma unroll
        for (int k = 0; k < 8; k++) s += ws[k];
        g_bsum[b] = s;
    }
}

__global__ void pscan_kernel() {
    int t = threadIdx.x;
    int v = (t < SNB) ? g_bsum[t] : 0;
    int excl = block_excl_scan256(v, t);
    if (t < SNB) g_bsum[t] = excl;
}

__global__ void pwrite_kernel() {
    int b = blockIdx.x, t = threadIdx.x;
    int i = b * SCH + t;
    int v = (i < N_NODES) ? g_deg[i] : 0;
    int excl = block_excl_scan256(v, t);
    int base = g_bsum[b];
    if (i < N_NODES) {
        g_rowptr[i] = base + excl;
        g_cursor[i] = base + excl;
    }
    if (i == N_NODES - 1) g_rowptr[N_NODES] = base + excl + v;
}

__global__ void fill_kernel(const void* __restrict__ ei) {
    int e = blockIdx.x * blockDim.x + threadIdx.x;
    if (e >= NE_TOT) return;
    int is64 = g_is64;
    int src, dst;
    if (e < N_EDGES) {
        src = edge_at(ei, e, is64);
        dst = edge_at(ei, N_EDGES + e, is64);
    } else {
        src = dst = e - N_EDGES;
    }
    int pos = atomicAdd(&g_cursor[dst], 1);
    if (pos >= 0 && pos < NE_TOT) g_col[pos] = src;
}

// ---------------------------------------------------------------------------
// Pipelined tf32 GEMM: C[M_PAD,N] = A[M,K] @ B[K,N]
// BM=128, BN=128, BK=16, cp.async double-buffered.
// 8 warps (4x2), each 32x64 output (2x4 m16n16k8 frags).
// GUARD: zero-fill A rows >= M via cp.async src-size=0 (for the x input).
// ---------------------------------------------------------------------------
#define GBM 128
#define GBN 128
#define GBK 16
#define GLA 20     // As row stride (floats)
#define GLB 136    // Bs row stride (floats)

template<bool GUARD>
__global__ __launch_bounds__(256) void tf32_gemm_big(
    const float* __restrict__ A, const float* __restrict__ B,
    float* __restrict__ C, int M, int N, int K)
{
    __shared__ float As[2][GBM][GLA];
    __shared__ float Bs[2][GBK][GLB];
    int tid  = threadIdx.x;
    int warp = tid >> 5;
    int wm   = warp >> 1;      // 0..3
    int wn   = warp & 1;       // 0..1
    int row0 = blockIdx.y * GBM;
    int col0 = blockIdx.x * GBN;

    uint32_t As_a = (uint32_t)__cvta_generic_to_shared(&As[0][0][0]);
    uint32_t Bs_a = (uint32_t)__cvta_generic_to_shared(&Bs[0][0][0]);

    wmma::fragment<wmma::accumulator, 16, 16, 8, float> acc[2][4];
    #pragma unroll
    for (int i = 0; i < 2; i++)
        #pragma unroll
        for (int j = 0; j < 4; j++)
            wmma::fill_fragment(acc[i][j], 0.0f);

    const int T = K / GBK;

    auto load_stage = [&](int it, int st) {
        int k0 = it * GBK;
        {   // A tile: 128 rows x 16 cols
            int r  = tid >> 1;
            int cq = (tid & 1) * 8;
            const float* gp = A + (size_t)(row0 + r) * K + k0 + cq;
            int sb = 16;
            if (GUARD && (row0 + r) >= M) sb = 0;
            uint32_t sa = As_a + (uint32_t)(((st * GBM + r) * GLA + cq) * 4);
            cp_async16(sa,      gp,     sb);
            cp_async16(sa + 16, gp + 4, sb);
        }
        {   // B tile: 16 rows x 128 cols
            int r  = tid >> 4;
            int cq = (tid & 15) * 8;
            const float* gp = B + (size_t)(k0 + r) * N + col0 + cq;
            uint32_t sa = Bs_a + (uint32_t)(((st * GBK + r) * GLB + cq) * 4);
            cp_async16(sa,      gp,     16);
            cp_async16(sa + 16, gp + 4, 16);
        }
        cp_commit();
    };

    load_stage(0, 0);
    for (int it = 0; it < T; it++) {
        int cur = it & 1;
        if (it + 1 < T) {
            load_stage(it + 1, (it + 1) & 1);
            asm volatile("cp.async.wait_group 1;\n");
        } else {
            asm volatile("cp.async.wait_group 0;\n");
        }
        __syncthreads();

        #pragma unroll
        for (int kk = 0; kk < GBK; kk += 8) {
            wmma::fragment<wmma::matrix_a, 16, 16, 8, wmma::precision::tf32, wmma::row_major> af[2];
            wmma::fragment<wmma::matrix_b, 16, 16, 8, wmma::precision::tf32, wmma::row_major> bf[4];
            #pragma unroll
            for (int i = 0; i < 2; i++) {
                wmma::load_matrix_sync(af[i], &As[cur][wm * 32 + i * 16][kk], GLA);
                #pragma unroll
                for (int u = 0; u < af[i].num_elements; u++)
                    af[i].x[u] = wmma::__float_to_tf32(af[i].x[u]);
            }
            #pragma unroll
            for (int j = 0; j < 4; j++) {
                wmma::load_matrix_sync(bf[j], &Bs[cur][kk][wn * 64 + j * 16], GLB);
                #pragma unroll
                for (int u = 0; u < bf[j].num_elements; u++)
                    bf[j].x[u] = wmma::__float_to_tf32(bf[j].x[u]);
            }
            #pragma unroll
            for (int i = 0; i < 2; i++)
                #pragma unroll
                for (int j = 0; j < 4; j++)
                    wmma::mma_sync(acc[i][j], af[i], bf[j], acc[i][j]);
        }
        __syncthreads();
    }

    #pragma unroll
    for (int i = 0; i < 2; i++)
        #pragma unroll
        for (int j = 0; j < 4; j++)
            wmma::store_matrix_sync(
                C + (size_t)(row0 + wm * 32 + i * 16) * N + col0 + wn * 64 + j * 16,
                acc[i][j], N, wmma::mem_row_major);
}

// ---------------------------------------------------------------------------
// Layer-2 GEMM: C[M_PAD,16] = A[M_PAD,512] @ B[512,16]  (A already ELU'd)
// BM=128, BN=16, BK=32; 8 warps, each 16 rows x 16 cols.
// ---------------------------------------------------------------------------
__global__ __launch_bounds__(256) void tf32_gemm16(
    const float* __restrict__ A, const float* __restrict__ B,
    float* __restrict__ C)
{
    __shared__ float As[128][36];
    __shared__ float Bs[32][20];
    int tid  = threadIdx.x;
    int warp = tid >> 5;
    int row0 = blockIdx.x * 128;

    wmma::fragment<wmma::accumulator, 16, 16, 8, float> acc;
    wmma::fill_fragment(acc, 0.0f);

    for (int k0 = 0; k0 < FEAT; k0 += 32) {
        #pragma unroll
        for (int i = tid; i < 1024; i += 256) {
            int r = i >> 3, q = (i & 7) << 2;
            *(float4*)&As[r][q] = *(const float4*)(A + (size_t)(row0 + r) * FEAT + k0 + q);
        }
        if (tid < 128) {
            int r = tid >> 2, q = (tid & 3) << 2;
            *(float4*)&Bs[r][q] = *(const float4*)(B + (size_t)(k0 + r) * 16 + q);
        }
        __syncthreads();
        #pragma unroll
        for (int kk = 0; kk < 32; kk += 8) {
            wmma::fragment<wmma::matrix_a, 16, 16, 8, wmma::precision::tf32, wmma::row_major> af;
            wmma::fragment<wmma::matrix_b, 16, 16, 8, wmma::precision::tf32, wmma::row_major> bf;
            wmma::load_matrix_sync(af, &As[warp * 16][kk], 36);
            #pragma unroll
            for (int u = 0; u < af.num_elements; u++) af.x[u] = wmma::__float_to_tf32(af.x[u]);
            wmma::load_matrix_sync(bf, &Bs[kk][0], 20);
            #pragma unroll
            for (int u = 0; u < bf.num_elements; u++) bf.x[u] = wmma::__float_to_tf32(bf.x[u]);
            wmma::mma_sync(acc, af, bf, acc);
        }
        __syncthreads();
    }
    wmma::store_matrix_sync(C + (size_t)(row0 + warp * 16) * 16, acc, 16, wmma::mem_row_major);
}

// ---------------------------------------------------------------------------
// Attention logit projections.
// ---------------------------------------------------------------------------
template<int H, int C>
__global__ void al_kernel(const float* __restrict__ h,
                          const float* __restrict__ a_s,
                          const float* __restrict__ a_d,
                          float* __restrict__ als, float* __restrict__ ald)
{
    int wid = (blockIdx.x * blockDim.x + threadIdx.x) >> 5;
    int lane = threadIdx.x & 31;
    if (wid >= N_NODES * H) return;
    int n = wid / H, hd = wid % H;
    const float* hr = h + (size_t)n * H * C + hd * C;
    float s = 0.f, d = 0.f;
    for (int c = lane; c < C; c += 32) {
        float v = hr[c];
        s = fmaf(v, a_s[hd * C + c], s);
        d = fmaf(v, a_d[hd * C + c], d);
    }
    #pragma unroll
    for (int o = 16; o; o >>= 1) {
        s += __shfl_xor_sync(0xFFFFFFFFu, s, o);
        d += __shfl_xor_sync(0xFFFFFFFFu, d, o);
    }
    if (lane == 0) { als[wid] = s; ald[wid] = d; }
}

// ---------------------------------------------------------------------------
// Softmax + aggregation (H=8, C=64), self-loop-shifted softmax, ELU fused.
// ---------------------------------------------------------------------------
template<bool DOELU>
__global__ __launch_bounds__(128) void agg_kernel(
    const float* __restrict__ h, const float* __restrict__ als,
    const float* __restrict__ ald, const float* __restrict__ bias,
    float* __restrict__ out)
{
    int n = blockIdx.x;
    int t = threadIdx.x;
    int hd = t >> 4;
    int c4 = (t & 15) << 2;
    int start = g_rowptr[n], end = g_rowptr[n + 1];

    float adv = ald[n * 8 + hd];
    float shift = lrelu(als[n * 8 + hd] + adv);

    float4 acc = make_float4(0.f, 0.f, 0.f, 0.f);
    float den = 0.f;
    for (int i = start; i < end; i++) {
        int s = g_col[i];
        float w = __expf(lrelu(als[s * 8 + hd] + adv) - shift);
        den += w;
        const float4 hv = *(const float4*)(h + (size_t)s * FEAT + hd * 64 + c4);
        acc.x = fmaf(w, hv.x, acc.x);
        acc.y = fmaf(w, hv.y, acc.y);
        acc.z = fmaf(w, hv.z, acc.z);
        acc.w = fmaf(w, hv.w, acc.w);
    }
    float inv = 1.f / den;
    int c = hd * 64 + c4;
    float* op = out + (size_t)n * FEAT + c;
    float r0 = acc.x * inv + bias[c + 0];
    float r1 = acc.y * inv + bias[c + 1];
    float r2 = acc.z * inv + bias[c + 2];
    float r3 = acc.w * inv + bias[c + 3];
    if (DOELU) { r0 = eluf(r0); r1 = eluf(r1); r2 = eluf(r2); r3 = eluf(r3); }
    op[0] = r0; op[1] = r1; op[2] = r2; op[3] = r3;
}

// Final aggregation (H=1, C=16). One warp per node.
__global__ __launch_bounds__(128) void agg_final_kernel(
    const float* __restrict__ h2, const float* __restrict__ als,
    const float* __restrict__ ald, const float* __restrict__ bias,
    float* __restrict__ out)
{
    int wid = (blockIdx.x * blockDim.x + threadIdx.x) >> 5;
    int lane = threadIdx.x & 31;
    if (wid >= N_NODES) return;
    int n = wid;
    int start = g_rowptr[n], end = g_rowptr[n + 1];
    float adv = ald[n];
    float shift = lrelu(als[n] + adv);
    float acc = 0.f, den = 0.f;
    for (int i = start; i < end; i++) {
        int s = g_col[i];
        float w = __expf(lrelu(als[s] + adv) - shift);
        den += w;
        if (lane < 16) acc = fmaf(w, h2[(size_t)s * 16 + lane], acc);
    }
    if (lane < 16) out[(size_t)n * 16 + lane] = acc / den + bias[lane];
}

// ---------------------------------------------------------------------------
// Launch
// ---------------------------------------------------------------------------
extern "C" void kernel_launch(void* const* d_in, const int* in_sizes, int n_in,
                              void* d_out, int out_size)
{
    const float* x    = (const float*)d_in[0];
    const void*  ei   = d_in[1];
    const float* W0   = (const float*)d_in[2];
    const float* a_s0 = (const float*)d_in[3];
    const float* a_d0 = (const float*)d_in[4];
    const float* b0   = (const float*)d_in[5];
    const float* W1   = (const float*)d_in[6];
    const float* a_s1 = (const float*)d_in[7];
    const float* a_d1 = (const float*)d_in[8];
    const float* b1   = (const float*)d_in[9];
    const float* W2   = (const float*)d_in[10];
    const float* a_s2 = (const float*)d_in[11];
    const float* a_d2 = (const float*)d_in[12];
    const float* b2   = (const float*)d_in[13];
    float*       out  = (float*)d_out;

    float *H, *O, *H2, *ALS, *ALD;
    cudaGetSymbolAddress((void**)&H,   g_H);
    cudaGetSymbolAddress((void**)&O,   g_O);
    cudaGetSymbolAddress((void**)&H2,  g_H2);
    cudaGetSymbolAddress((void**)&ALS, g_als);
    cudaGetSymbolAddress((void**)&ALD, g_ald);

    // --- CSR by destination ---
    zero_detect_kernel<<<(N_NODES + 255) / 256, 256>>>((const int*)ei);
    count_kernel<<<(NE_TOT + 255) / 256, 256>>>(ei);
    psum_kernel<<<SNB, SCH>>>();
    pscan_kernel<<<1, 256>>>();
    pwrite_kernel<<<SNB, SCH>>>();
    fill_kernel<<<(NE_TOT + 255) / 256, 256>>>(ei);

    dim3 gg(FEAT / GBN, M_PAD / GBM);   // (4, 391)

    // --- Layer 0 ---
    tf32_gemm_big<true><<<gg, 256>>>(x, W0, H, N_NODES, FEAT, F_IN);
    al_kernel<HEADS, HID><<<(N_NODES * HEADS * 32 + 255) / 256, 256>>>(H, a_s0, a_d0, ALS, ALD);
    agg_kernel<true><<<N_NODES, 128>>>(H, ALS, ALD, b0, O);   // writes ELU'd

    // --- Layer 1 ---
    tf32_gemm_big<false><<<gg, 256>>>(O, W1, H, M_PAD, FEAT, FEAT);
    al_kernel<HEADS, HID><<<(N_NODES * HEADS * 32 + 255) / 256, 256>>>(H, a_s1, a_d1, ALS, ALD);
    agg_kernel<true><<<N_NODES, 128>>>(H, ALS, ALD, b1, O);   // writes ELU'd

    // --- Layer 2 ---
    tf32_gemm16<<<M_PAD / 128, 256>>>(O, W2, H2);
    al_kernel<1, N_CLASSES><<<(N_NODES * 32 + 255) / 256, 256>>>(H2, a_s2, a_d2, ALS, ALD);
    agg_final_kernel<<<(N_NODES * 32 + 127) / 128, 128>>>(H2, ALS, ALD, b2, out);
}

// round 5
// speedup vs baseline: 2.3034x; 1.0866x over previous
#include <cuda_runtime.h>
#include <cuda_bf16.h>
#include <cuda_fp16.h>
#include <mma.h>
#include <math.h>
#include <stdint.h>

using namespace nvcuda;

#define N_NODES 50000
#define M_PAD   50048
#define N_EDGES 400000
#define NE_TOT  (N_EDGES + N_NODES)
#define F_IN    128
#define HID     64
#define HEADS   8
#define FEAT    (HEADS * HID)          // 512
#define N_CLASSES 16
#define NEG_SLOPE 0.2f

// ---------------------------------------------------------------------------
// Static scratch
// ---------------------------------------------------------------------------
__device__ float  g_H  [(size_t)M_PAD * FEAT];
__device__ float  g_O  [(size_t)M_PAD * FEAT];       // ELU'd aggregation output
__device__ __half g_h16[(size_t)M_PAD * FEAT];       // fp16 mirror of g_H for gather
__device__ float  g_H2 [(size_t)M_PAD * N_CLASSES];
__device__ float  g_als[(size_t)N_NODES * HEADS];
__device__ float  g_ald[(size_t)N_NODES * HEADS];
__device__ int    g_deg   [N_NODES];
__device__ int    g_rowptr[N_NODES + 1];
__device__ int    g_cursor[N_NODES];
__device__ int    g_col   [NE_TOT];
__device__ int    g_bsum  [256];
__device__ int    g_is64;

__device__ __forceinline__ float eluf(float x)   { return x > 0.f ? x : expm1f(x); }
__device__ __forceinline__ float lrelu(float x)  { return x > 0.f ? x : NEG_SLOPE * x; }
__device__ __forceinline__ int clampi(int v) {
    return (v < 0) ? 0 : (v >= N_NODES ? N_NODES - 1 : v);
}
__device__ __forceinline__ int edge_at(const void* ei, int idx, int is64) {
    if (is64) return clampi((int)((const long long*)ei)[idx]);
    return clampi(((const int*)ei)[idx]);
}

__device__ __forceinline__ void cp_async16(uint32_t saddr, const void* gptr, int src_bytes) {
    asm volatile("cp.async.cg.shared.global [%0], [%1], 16, %2;\n"
                 :: "r"(saddr), "l"(gptr), "r"(src_bytes));
}
__device__ __forceinline__ void cp_commit() {
    asm volatile("cp.async.commit_group;\n");
}

// ---------------------------------------------------------------------------
// zero degrees + dtype probe (int64 layout => odd 32-bit words all zero)
// ---------------------------------------------------------------------------
__global__ void zero_detect_kernel(const int* __restrict__ ei_raw) {
    int i = blockIdx.x * blockDim.x + threadIdx.x;
    if (i < N_NODES) g_deg[i] = 0;
    if (i == 0) {
        int any_nonzero = 0;
        #pragma unroll 1
        for (int k = 0; k < 64; k++) any_nonzero |= ei_raw[2 * k + 1];
        g_is64 = (any_nonzero == 0) ? 1 : 0;
    }
}

__global__ void count_kernel(const void* __restrict__ ei) {
    int e = blockIdx.x * blockDim.x + threadIdx.x;
    if (e >= NE_TOT) return;
    int is64 = g_is64;
    int dst = (e < N_EDGES) ? edge_at(ei, N_EDGES + e, is64) : (e - N_EDGES);
    atomicAdd(&g_deg[dst], 1);
}

// ---------------------------------------------------------------------------
// Parallel exclusive scan (2 kernels): per-block sums -> per-block write with
// direct prefix over the 196 block sums.
// ---------------------------------------------------------------------------
#define SCH 256
#define SNB ((N_NODES + SCH - 1) / SCH)   // 196

__global__ void psum_kernel() {
    int b = blockIdx.x, t = threadIdx.x;
    int i = b * SCH + t;
    int v = (i < N_NODES) ? g_deg[i] : 0;
    __shared__ int ws[8];
    int lane = t & 31, w = t >> 5;
    #pragma unroll
    for (int o = 16; o; o >>= 1) v += __shfl_xor_sync(0xFFFFFFFFu, v, o);
    if (lane == 0) ws[w] = v;
    __syncthreads();
    if (t == 0) {
        int s = 0;
        #pragma unroll
        for (int k = 0; k < 8; k++) s += ws[k];
        g_bsum[b] = s;
    }
}

__global__ void pwrite_kernel() {
    int b = blockIdx.x, t = threadIdx.x;
    __shared__ int ws[8];
    __shared__ int sbase;
    int lane = t & 31, w = t >> 5;

    // base = sum of g_bsum[0..b-1]
    int pv = (t < b) ? g_bsum[t] : 0;
    int rv = pv;
    #pragma unroll
    for (int o = 16; o; o >>= 1) rv += __shfl_xor_sync(0xFFFFFFFFu, rv, o);
    if (lane == 0) ws[w] = rv;
    __syncthreads();
    if (t == 0) {
        int s = 0;
        #pragma unroll
        for (int k = 0; k < 8; k++) s += ws[k];
        sbase = s;
    }
    __syncthreads();

    // local exclusive scan of this block's degrees
    int i = b * SCH + t;
    int v = (i < N_NODES) ? g_deg[i] : 0;
    int x = v;
    #pragma unroll
    for (int o = 1; o < 32; o <<= 1) {
        int u = __shfl_up_sync(0xFFFFFFFFu, x, o);
        if (lane >= o) x += u;
    }
    __syncthreads();
    if (lane == 31) ws[w] = x;
    __syncthreads();
    int wbase = 0;
    #pragma unroll
    for (int k = 0; k < 8; k++) if (k < w) wbase += ws[k];
    int excl = sbase + wbase + x - v;
    if (i < N_NODES) {
        g_rowptr[i] = excl;
        g_cursor[i] = excl;
    }
    if (i == N_NODES - 1) g_rowptr[N_NODES] = excl + v;
}

__global__ void fill_kernel(const void* __restrict__ ei) {
    int e = blockIdx.x * blockDim.x + threadIdx.x;
    if (e >= NE_TOT) return;
    int is64 = g_is64;
    int src, dst;
    if (e < N_EDGES) {
        src = edge_at(ei, e, is64);
        dst = edge_at(ei, N_EDGES + e, is64);
    } else {
        src = dst = e - N_EDGES;
    }
    int pos = atomicAdd(&g_cursor[dst], 1);
    if (pos >= 0 && pos < NE_TOT) g_col[pos] = src;
}

// ---------------------------------------------------------------------------
// Pipelined tf32 GEMM (3-stage cp.async): C[M_PAD,N] = A[M,K] @ B[K,N]
// BM=128, BN=128, BK=16; 8 warps (4x2), each 32x64 output.
// ---------------------------------------------------------------------------
#define GBM 128
#define GBN 128
#define GBK 16
#define GLA 20
#define GLB 136
#define GST 3

template<bool GUARD>
__global__ __launch_bounds__(256) void tf32_gemm_big(
    const float* __restrict__ A, const float* __restrict__ B,
    float* __restrict__ C, int M, int N, int K)
{
    __shared__ float As[GST][GBM][GLA];
    __shared__ float Bs[GST][GBK][GLB];
    int tid  = threadIdx.x;
    int warp = tid >> 5;
    int wm   = warp >> 1;
    int wn   = warp & 1;
    int row0 = blockIdx.y * GBM;
    int col0 = blockIdx.x * GBN;

    uint32_t As_a = (uint32_t)__cvta_generic_to_shared(&As[0][0][0]);
    uint32_t Bs_a = (uint32_t)__cvta_generic_to_shared(&Bs[0][0][0]);

    wmma::fragment<wmma::accumulator, 16, 16, 8, float> acc[2][4];
    #pragma unroll
    for (int i = 0; i < 2; i++)
        #pragma unroll
        for (int j = 0; j < 4; j++)
            wmma::fill_fragment(acc[i][j], 0.0f);

    const int T = K / GBK;

    auto load_stage = [&](int it) {
        int st = it % GST;
        int k0 = it * GBK;
        {
            int r  = tid >> 1;
            int cq = (tid & 1) * 8;
            const float* gp = A + (size_t)(row0 + r) * K + k0 + cq;
            int sb = 16;
            if (GUARD && (row0 + r) >= M) sb = 0;
            uint32_t sa = As_a + (uint32_t)(((st * GBM + r) * GLA + cq) * 4);
            cp_async16(sa,      gp,     sb);
            cp_async16(sa + 16, gp + 4, sb);
        }
        {
            int r  = tid >> 4;
            int cq = (tid & 15) * 8;
            const float* gp = B + (size_t)(k0 + r) * N + col0 + cq;
            uint32_t sa = Bs_a + (uint32_t)(((st * GBK + r) * GLB + cq) * 4);
            cp_async16(sa,      gp,     16);
            cp_async16(sa + 16, gp + 4, 16);
        }
        cp_commit();
    };

    load_stage(0);
    if (T > 1) load_stage(1);
    for (int it = 0; it < T; it++) {
        int cur = it % GST;
        if (it + 2 < T) {
            load_stage(it + 2);
            asm volatile("cp.async.wait_group 2;\n");
        } else if (it + 1 < T) {
            asm volatile("cp.async.wait_group 1;\n");
        } else {
            asm volatile("cp.async.wait_group 0;\n");
        }
        __syncthreads();

        #pragma unroll
        for (int kk = 0; kk < GBK; kk += 8) {
            wmma::fragment<wmma::matrix_a, 16, 16, 8, wmma::precision::tf32, wmma::row_major> af[2];
            wmma::fragment<wmma::matrix_b, 16, 16, 8, wmma::precision::tf32, wmma::row_major> bf[4];
            #pragma unroll
            for (int i = 0; i < 2; i++) {
                wmma::load_matrix_sync(af[i], &As[cur][wm * 32 + i * 16][kk], GLA);
                #pragma unroll
                for (int u = 0; u < af[i].num_elements; u++)
                    af[i].x[u] = wmma::__float_to_tf32(af[i].x[u]);
            }
            #pragma unroll
            for (int j = 0; j < 4; j++) {
                wmma::load_matrix_sync(bf[j], &Bs[cur][kk][wn * 64 + j * 16], GLB);
                #pragma unroll
                for (int u = 0; u < bf[j].num_elements; u++)
                    bf[j].x[u] = wmma::__float_to_tf32(bf[j].x[u]);
            }
            #pragma unroll
            for (int i = 0; i < 2; i++)
                #pragma unroll
                for (int j = 0; j < 4; j++)
                    wmma::mma_sync(acc[i][j], af[i], bf[j], acc[i][j]);
        }
        __syncthreads();
    }

    #pragma unroll
    for (int i = 0; i < 2; i++)
        #pragma unroll
        for (int j = 0; j < 4; j++)
            wmma::store_matrix_sync(
                C + (size_t)(row0 + wm * 32 + i * 16) * N + col0 + wn * 64 + j * 16,
                acc[i][j], N, wmma::mem_row_major);
}

// ---------------------------------------------------------------------------
// Layer-2 GEMM: C[M_PAD,16] = A[M_PAD,512] @ B[512,16]
// ---------------------------------------------------------------------------
__global__ __launch_bounds__(256) void tf32_gemm16(
    const float* __restrict__ A, const float* __restrict__ B,
    float* __restrict__ C)
{
    __shared__ float As[128][36];
    __shared__ float Bs[32][20];
    int tid  = threadIdx.x;
    int warp = tid >> 5;
    int row0 = blockIdx.x * 128;

    wmma::fragment<wmma::accumulator, 16, 16, 8, float> acc;
    wmma::fill_fragment(acc, 0.0f);

    for (int k0 = 0; k0 < FEAT; k0 += 32) {
        #pragma unroll
        for (int i = tid; i < 1024; i += 256) {
            int r = i >> 3, q = (i & 7) << 2;
            *(float4*)&As[r][q] = *(const float4*)(A + (size_t)(row0 + r) * FEAT + k0 + q);
        }
        if (tid < 128) {
            int r = tid >> 2, q = (tid & 3) << 2;
            *(float4*)&Bs[r][q] = *(const float4*)(B + (size_t)(k0 + r) * 16 + q);
        }
        __syncthreads();
        #pragma unroll
        for (int kk = 0; kk < 32; kk += 8) {
            wmma::fragment<wmma::matrix_a, 16, 16, 8, wmma::precision::tf32, wmma::row_major> af;
            wmma::fragment<wmma::matrix_b, 16, 16, 8, wmma::precision::tf32, wmma::row_major> bf;
            wmma::load_matrix_sync(af, &As[warp * 16][kk], 36);
            #pragma unroll
            for (int u = 0; u < af.num_elements; u++) af.x[u] = wmma::__float_to_tf32(af.x[u]);
            wmma::load_matrix_sync(bf, &Bs[kk][0], 20);
            #pragma unroll
            for (int u = 0; u < bf.num_elements; u++) bf.x[u] = wmma::__float_to_tf32(bf.x[u]);
            wmma::mma_sync(acc, af, bf, acc);
        }
        __syncthreads();
    }
    wmma::store_matrix_sync(C + (size_t)(row0 + warp * 16) * 16, acc, 16, wmma::mem_row_major);
}

// ---------------------------------------------------------------------------
// Attention logit projections (+ optional fp16 mirror of h).
// One warp per (node, head).
// ---------------------------------------------------------------------------
template<int H, int C, bool W16>
__global__ void al_kernel(const float* __restrict__ h,
                          const float* __restrict__ a_s,
                          const float* __restrict__ a_d,
                          float* __restrict__ als, float* __restrict__ ald,
                          __half* __restrict__ h16)
{
    int wid = (blockIdx.x * blockDim.x + threadIdx.x) >> 5;
    int lane = threadIdx.x & 31;
    if (wid >= N_NODES * H) return;
    int n = wid / H, hd = wid % H;
    const float* hr = h + (size_t)n * H * C + hd * C;
    __half* hw = W16 ? (h16 + (size_t)n * H * C + hd * C) : (__half*)0;
    float s = 0.f, d = 0.f;
    #pragma unroll
    for (int c = lane; c < C; c += 32) {
        float v = hr[c];
        if (W16) hw[c] = __float2half(v);
        s = fmaf(v, a_s[hd * C + c], s);
        d = fmaf(v, a_d[hd * C + c], d);
    }
    #pragma unroll
    for (int o = 16; o; o >>= 1) {
        s += __shfl_xor_sync(0xFFFFFFFFu, s, o);
        d += __shfl_xor_sync(0xFFFFFFFFu, d, o);
    }
    if (lane == 0) { als[wid] = s; ald[wid] = d; }
}

// ---------------------------------------------------------------------------
// Softmax + aggregation (H=8, C=64), self-shifted softmax, ELU fused,
// fp16 gather of h.
// ---------------------------------------------------------------------------
template<bool DOELU>
__global__ __launch_bounds__(128) void agg_kernel(
    const __half* __restrict__ h16, const float* __restrict__ als,
    const float* __restrict__ ald, const float* __restrict__ bias,
    float* __restrict__ out)
{
    int n = blockIdx.x;
    int t = threadIdx.x;
    int hd = t >> 4;
    int c4 = (t & 15) << 2;
    int start = g_rowptr[n], end = g_rowptr[n + 1];

    float adv = ald[n * 8 + hd];
    float shift = lrelu(als[n * 8 + hd] + adv);

    float4 acc = make_float4(0.f, 0.f, 0.f, 0.f);
    float den = 0.f;
    for (int i = start; i < end; i++) {
        int s = g_col[i];
        float w = __expf(lrelu(als[s * 8 + hd] + adv) - shift);
        den += w;
        uint2 u = *(const uint2*)(h16 + (size_t)s * FEAT + hd * 64 + c4);
        float2 f0 = __half22float2(*reinterpret_cast<__half2*>(&u.x));
        float2 f1 = __half22float2(*reinterpret_cast<__half2*>(&u.y));
        acc.x = fmaf(w, f0.x, acc.x);
        acc.y = fmaf(w, f0.y, acc.y);
        acc.z = fmaf(w, f1.x, acc.z);
        acc.w = fmaf(w, f1.y, acc.w);
    }
    float inv = 1.f / den;
    int c = hd * 64 + c4;
    float* op = out + (size_t)n * FEAT + c;
    float r0 = acc.x * inv + bias[c + 0];
    float r1 = acc.y * inv + bias[c + 1];
    float r2 = acc.z * inv + bias[c + 2];
    float r3 = acc.w * inv + bias[c + 3];
    if (DOELU) { r0 = eluf(r0); r1 = eluf(r1); r2 = eluf(r2); r3 = eluf(r3); }
    op[0] = r0; op[1] = r1; op[2] = r2; op[3] = r3;
}

// Final aggregation (H=1, C=16). One warp per node.
__global__ __launch_bounds__(128) void agg_final_kernel(
    const float* __restrict__ h2, const float* __restrict__ als,
    const float* __restrict__ ald, const float* __restrict__ bias,
    float* __restrict__ out)
{
    int wid = (blockIdx.x * blockDim.x + threadIdx.x) >> 5;
    int lane = threadIdx.x & 31;
    if (wid >= N_NODES) return;
    int n = wid;
    int start = g_rowptr[n], end = g_rowptr[n + 1];
    float adv = ald[n];
    float shift = lrelu(als[n] + adv);
    float acc = 0.f, den = 0.f;
    for (int i = start; i < end; i++) {
        int s = g_col[i];
        float w = __expf(lrelu(als[s] + adv) - shift);
        den += w;
        if (lane < 16) acc = fmaf(w, h2[(size_t)s * 16 + lane], acc);
    }
    if (lane < 16) out[(size_t)n * 16 + lane] = acc / den + bias[lane];
}

// ---------------------------------------------------------------------------
// Launch
// ---------------------------------------------------------------------------
extern "C" void kernel_launch(void* const* d_in, const int* in_sizes, int n_in,
                              void* d_out, int out_size)
{
    const float* x    = (const float*)d_in[0];
    const void*  ei   = d_in[1];
    const float* W0   = (const float*)d_in[2];
    const float* a_s0 = (const float*)d_in[3];
    const float* a_d0 = (const float*)d_in[4];
    const float* b0   = (const float*)d_in[5];
    const float* W1   = (const float*)d_in[6];
    const float* a_s1 = (const float*)d_in[7];
    const float* a_d1 = (const float*)d_in[8];
    const float* b1   = (const float*)d_in[9];
    const float* W2   = (const float*)d_in[10];
    const float* a_s2 = (const float*)d_in[11];
    const float* a_d2 = (const float*)d_in[12];
    const float* b2   = (const float*)d_in[13];
    float*       out  = (float*)d_out;

    float *H, *O, *H2, *ALS, *ALD;
    __half* H16;
    cudaGetSymbolAddress((void**)&H,   g_H);
    cudaGetSymbolAddress((void**)&O,   g_O);
    cudaGetSymbolAddress((void**)&H16, g_h16);
    cudaGetSymbolAddress((void**)&H2,  g_H2);
    cudaGetSymbolAddress((void**)&ALS, g_als);
    cudaGetSymbolAddress((void**)&ALD, g_ald);

    // --- CSR by destination (5 launches; GEMM0 is launch #6 for ncu -s 5) ---
    zero_detect_kernel<<<(N_NODES + 255) / 256, 256>>>((const int*)ei);
    count_kernel<<<(NE_TOT + 255) / 256, 256>>>(ei);
    psum_kernel<<<SNB, SCH>>>();
    pwrite_kernel<<<SNB, SCH>>>();
    fill_kernel<<<(NE_TOT + 255) / 256, 256>>>(ei);

    dim3 gg(FEAT / GBN, M_PAD / GBM);   // (4, 391)

    // --- Layer 0 ---
    tf32_gemm_big<true><<<gg, 256>>>(x, W0, H, N_NODES, FEAT, F_IN);
    al_kernel<HEADS, HID, true><<<(N_NODES * HEADS * 32 + 255) / 256, 256>>>(H, a_s0, a_d0, ALS, ALD, H16);
    agg_kernel<true><<<N_NODES, 128>>>(H16, ALS, ALD, b0, O);

    // --- Layer 1 ---
    tf32_gemm_big<false><<<gg, 256>>>(O, W1, H, M_PAD, FEAT, FEAT);
    al_kernel<HEADS, HID, true><<<(N_NODES * HEADS * 32 + 255) / 256, 256>>>(H, a_s1, a_d1, ALS, ALD, H16);
    agg_kernel<true><<<N_NODES, 128>>>(H16, ALS, ALD, b1, O);

    // --- Layer 2 ---
    tf32_gemm16<<<M_PAD / 128, 256>>>(O, W2, H2);
    al_kernel<1, N_CLASSES, false><<<(N_NODES * 32 + 255) / 256, 256>>>(H2, a_s2, a_d2, ALS, ALD, (__half*)0);
    agg_final_kernel<<<(N_NODES * 32 + 127) / 128, 128>>>(H2, ALS, ALD, b2, out);
}